// round 10
// baseline (speedup 1.0000x reference)
#include <cuda_runtime.h>
#include <cstdint>

// GRU: B=256, T=2048, I=10, H=64 (PyTorch gate order r,z,n).
// grid=128, 768 threads/CTA = 2 batches x 384 threads.
// Each gate row handled by a thread PAIR (32-wide half-dots + shfl.bfly),
// FFMA2 packed dots with 4 accumulator chains (depth 4), h in SMEM,
// cp.async double-buffered input, per-half named barriers.

#define BB 256
#define TT 2048
#define II 10
#define HH 64
#define GG 192              // 3*H rows
#define TPB 384             // threads per batch (2 per row)
#define NT (2 * TPB)        // 768
#define CHUNK 64
#define NCH (TT / CHUNK)
#define CPOPS ((CHUNK * II * 4) / 16)   // 160 x 16B cp.async per chunk per batch

__device__ __forceinline__ uint64_t fma2(uint64_t a, uint64_t b, uint64_t c) {
    uint64_t d;
    asm("fma.rn.f32x2 %0, %1, %2, %3;" : "=l"(d) : "l"(a), "l"(b), "l"(c));
    return d;
}
__device__ __forceinline__ void cp16(uint32_t saddr, const void* gptr) {
    asm volatile("cp.async.ca.shared.global [%0], [%1], 16;" :: "r"(saddr), "l"(gptr));
}
__device__ __forceinline__ float f2lo(uint64_t v) { return __uint_as_float((uint32_t)v); }
__device__ __forceinline__ float f2hi(uint64_t v) { return __uint_as_float((uint32_t)(v >> 32)); }
__device__ __forceinline__ void barh(int half) {
    asm volatile("bar.sync %0, %1;" :: "r"(half + 1), "r"(TPB) : "memory");
}
__device__ __forceinline__ float sigm(float x) { return 1.0f / (1.0f + __expf(-x)); }
__device__ __forceinline__ float tanh_fast(float x) {
    return 1.0f - 2.0f / (1.0f + __expf(2.0f * x));
}

__global__ __launch_bounds__(NT, 1) void gru_kernel(
    const float* __restrict__ noise,   // (B, T, I)
    const float* __restrict__ w_ih,    // (3H, I)
    const float* __restrict__ w_hh,    // (3H, H)
    const float* __restrict__ b_ih,    // (3H)
    const float* __restrict__ b_hh,    // (3H)
    float* __restrict__ out)           // (B, T, H)
{
    const int half = (threadIdx.x >= TPB) ? 1 : 0;
    const int t = threadIdx.x - half * TPB;   // 0..383 within batch
    const int r = t >> 1;                     // gate row 0..191
    const int side = t & 1;                   // 0: h[0:32), 1: h[32:64)
    const int b = blockIdx.x * 2 + half;

    __shared__ __align__(16) float hs[2][HH];
    __shared__ __align__(16) float pre[2][4][HH];        // r, z, n_hpart, n_xpart
    __shared__ __align__(16) float xs[2][2][CHUNK * II];

    // --- this thread's half of the w_hh row: 32 floats = 16 f32x2 pairs ---
    uint64_t wp[16];
    {
        const uint64_t* wrow =
            reinterpret_cast<const uint64_t*>(w_hh + (size_t)r * HH + side * 32);
        #pragma unroll
        for (int k = 0; k < 16; k++) wp[k] = wrow[k];
    }
    // this thread's half of the w_ih row (5 scalars)
    float wi[5];
    #pragma unroll
    for (int j = 0; j < 5; j++) wi[j] = w_ih[(size_t)r * II + side * 5 + j];
    const float bi = b_ih[r];
    const float bh = b_hh[r];

    if (t < HH) hs[half][t] = 0.0f;
    float h_reg = 0.0f;   // act thread t<HH caches h[t]

    const float* xg = noise + (size_t)b * TT * II;
    float* outb = out + (size_t)b * TT * HH;

    if (t < CPOPS)
        cp16((uint32_t)__cvta_generic_to_shared(&xs[half][0][t * 4]), xg + t * 4);
    asm volatile("cp.async.commit_group;");

    int buf = 0;
    #pragma unroll 1
    for (int c = 0; c < NCH; ++c) {
        if (c + 1 < NCH && t < CPOPS)
            cp16((uint32_t)__cvta_generic_to_shared(&xs[half][buf ^ 1][t * 4]),
                 xg + (size_t)(c + 1) * CHUNK * II + t * 4);
        asm volatile("cp.async.commit_group;");
        asm volatile("cp.async.wait_group 1;");
        barh(half);

        // input half-dot for step 0
        float px;
        {
            const float* x = &xs[half][buf][side * 5];
            float a = 0.0f;
            #pragma unroll
            for (int j = 0; j < 5; j++) a = fmaf(wi[j], x[j], a);
            px = a;
        }

        #pragma unroll 1
        for (int s = 0; s < CHUNK; ++s) {
            // ---- recurrent half-dot over 32 floats: 8x LDS.128, 16 FFMA2,
            //      4 accumulator chains (depth 4) ----
            const ulonglong2* hp =
                reinterpret_cast<const ulonglong2*>(&hs[half][side * 32]);
            uint64_t a0 = 0ull, a1 = 0ull, a2 = 0ull, a3 = 0ull;
            #pragma unroll
            for (int k = 0; k < 4; k++) {
                ulonglong2 v0 = hp[2 * k];
                ulonglong2 v1 = hp[2 * k + 1];
                a0 = fma2(wp[4 * k],     v0.x, a0);
                a1 = fma2(wp[4 * k + 1], v0.y, a1);
                a2 = fma2(wp[4 * k + 2], v1.x, a2);
                a3 = fma2(wp[4 * k + 3], v1.y, a3);
            }
            uint64_t aa = fma2(a2, 0ull, a0);   // placeholder-free add below instead
            // combine 4 chains (scalar adds; tree)
            float ph = ((f2lo(a0) + f2hi(a0)) + (f2lo(a1) + f2hi(a1)))
                     + ((f2lo(a2) + f2hi(a2)) + (f2lo(a3) + f2hi(a3)));
            (void)aa;

            // combine the two halves (pair = adjacent lanes of same warp)
            float ph_tot = ph + __shfl_xor_sync(0xffffffffu, ph, 1);
            float px_tot = px + __shfl_xor_sync(0xffffffffu, px, 1);

            if (side == 0) {
                if (r < HH)            pre[half][0][r] = ph_tot + px_tot + bh + bi;
                else if (r < 2 * HH)   pre[half][1][r - HH] = ph_tot + px_tot + bh + bi;
                else {
                    pre[half][2][r - 2 * HH] = ph_tot + bh;   // n h-part
                    pre[half][3][r - 2 * HH] = px_tot + bi;   // n x-part
                }
            }
            barh(half);

            // pipelined input half-dot for next step (h-independent)
            if (s + 1 < CHUNK) {
                const float* x = &xs[half][buf][(s + 1) * II + side * 5];
                float a = 0.0f;
                #pragma unroll
                for (int j = 0; j < 5; j++) a = fmaf(wi[j], x[j], a);
                px = a;
            }

            // ---- activation + h update: threads t < 64 ----
            if (t < HH) {
                float rg = sigm(pre[half][0][t]);
                float zg = sigm(pre[half][1][t]);
                float ng = tanh_fast(pre[half][3][t] + rg * pre[half][2][t]);
                float hnew = ng + zg * (h_reg - ng);
                h_reg = hnew;
                hs[half][t] = hnew;
                outb[(size_t)(c * CHUNK + s) * HH + t] = hnew;
            }
            barh(half);
        }
        buf ^= 1;
    }
}

extern "C" void kernel_launch(void* const* d_in, const int* in_sizes, int n_in,
                              void* d_out, int out_size) {
    const float* noise = (const float*)d_in[0];
    const float* w_ih  = (const float*)d_in[1];
    const float* w_hh  = (const float*)d_in[2];
    const float* b_ih  = (const float*)d_in[3];
    const float* b_hh  = (const float*)d_in[4];
    float* out = (float*)d_out;
    gru_kernel<<<BB / 2, NT>>>(noise, w_ih, w_hh, b_ih, b_hh, out);
}

// round 13
// speedup vs baseline: 1.3009x; 1.3009x over previous
#include <cuda_runtime.h>
#include <cstdint>

// GRU: B=256, T=2048, I=10, H=64 (PyTorch gate order r,z,n).
// grid=128 CTAs x 256 threads = 2 batches x 128 threads.
// Per batch: threads 0-63 own h-index i with BOTH w_hr and w_hz rows in
// registers (r,z sigmoids are local, pre-barrier); threads 64-127 own w_hn
// row i, ship hn/xn through SMEM. One handoff barrier + one publish barrier
// per step, 128-thread (4-warp) barrier groups. f32x2 packed dots,
// cp.async double-buffered input chunks.

#define BB 256
#define TT 2048
#define II 10
#define HH 64
#define TPB 128             // threads per batch
#define NT (2 * TPB)        // 256
#define CHUNK 64
#define NCH (TT / CHUNK)    // 32
#define CPOPS ((CHUNK * II * 4) / 16)   // 160 x 16B per chunk per batch

__device__ __forceinline__ uint64_t fma2(uint64_t a, uint64_t b, uint64_t c) {
    uint64_t d;
    asm("fma.rn.f32x2 %0, %1, %2, %3;" : "=l"(d) : "l"(a), "l"(b), "l"(c));
    return d;
}
__device__ __forceinline__ void cp16(uint32_t saddr, const void* gptr) {
    asm volatile("cp.async.ca.shared.global [%0], [%1], 16;" :: "r"(saddr), "l"(gptr));
}
__device__ __forceinline__ float f2lo(uint64_t v) { return __uint_as_float((uint32_t)v); }
__device__ __forceinline__ float f2hi(uint64_t v) { return __uint_as_float((uint32_t)(v >> 32)); }
__device__ __forceinline__ void barh(int half) {
    asm volatile("bar.sync %0, %1;" :: "r"(half + 1), "r"(TPB) : "memory");
}
__device__ __forceinline__ float sigm(float x) { return 1.0f / (1.0f + __expf(-x)); }
__device__ __forceinline__ float tanh_fast(float x) {
    return 1.0f - 2.0f / (1.0f + __expf(2.0f * x));
}

// 64-wide packed dot: wp = 32 f32x2 pairs, hv = 16 x ulonglong2 (h vector)
__device__ __forceinline__ float dot64(const uint64_t* __restrict__ wp,
                                       const ulonglong2* __restrict__ hv) {
    uint64_t a0 = 0ull, a1 = 0ull, a2 = 0ull, a3 = 0ull;
    #pragma unroll
    for (int k = 0; k < 8; k++) {
        ulonglong2 v0 = hv[2 * k];
        ulonglong2 v1 = hv[2 * k + 1];
        a0 = fma2(wp[4 * k],     v0.x, a0);
        a1 = fma2(wp[4 * k + 1], v0.y, a1);
        a2 = fma2(wp[4 * k + 2], v1.x, a2);
        a3 = fma2(wp[4 * k + 3], v1.y, a3);
    }
    return ((f2lo(a0) + f2hi(a0)) + (f2lo(a1) + f2hi(a1)))
         + ((f2lo(a2) + f2hi(a2)) + (f2lo(a3) + f2hi(a3)));
}

// 10-wide packed input dot: wip = 5 f32x2 pairs, x = 10 floats (8B aligned)
__device__ __forceinline__ float dot10(const uint64_t* __restrict__ wip,
                                       const float* __restrict__ x) {
    const uint64_t* xp = reinterpret_cast<const uint64_t*>(x);
    uint64_t a0 = 0ull, a1 = 0ull;
    a0 = fma2(wip[0], xp[0], a0);
    a1 = fma2(wip[1], xp[1], a1);
    a0 = fma2(wip[2], xp[2], a0);
    a1 = fma2(wip[3], xp[3], a1);
    a0 = fma2(wip[4], xp[4], a0);
    return (f2lo(a0) + f2hi(a0)) + (f2lo(a1) + f2hi(a1));
}

__global__ __launch_bounds__(NT, 1) void gru_kernel(
    const float* __restrict__ noise,   // (B, T, I)
    const float* __restrict__ w_ih,    // (3H, I)
    const float* __restrict__ w_hh,    // (3H, H)
    const float* __restrict__ b_ih,    // (3H)
    const float* __restrict__ b_hh,    // (3H)
    float* __restrict__ out)           // (B, T, H)
{
    const int half = threadIdx.x >> 7;        // 0/1: which batch in CTA
    const int t = threadIdx.x & (TPB - 1);    // 0..127
    const int i = t & (HH - 1);               // h index 0..63
    const bool is_rz = (t < HH);
    const int b = blockIdx.x * 2 + half;

    __shared__ __align__(16) float hs[2][HH];
    __shared__ __align__(16) float nh[2][HH];     // n-gate h-part
    __shared__ __align__(16) float nx[2][HH];     // n-gate x-part
    __shared__ __align__(16) float xs[2][2][CHUNK * II];

    // ---- weights into registers ----
    // rz threads: rows i (r) and 64+i (z). n threads: row 128+i (n).
    const int row0 = is_rz ? i : (2 * HH + i);
    uint64_t w0[32];
    {
        const uint64_t* p = reinterpret_cast<const uint64_t*>(w_hh + (size_t)row0 * HH);
        #pragma unroll
        for (int k = 0; k < 32; k++) w0[k] = p[k];
    }
    uint64_t w1[32];
    if (is_rz) {
        const uint64_t* p = reinterpret_cast<const uint64_t*>(w_hh + (size_t)(HH + i) * HH);
        #pragma unroll
        for (int k = 0; k < 32; k++) w1[k] = p[k];
    }
    uint64_t wi0[5], wi1[5];
    {
        const uint64_t* p = reinterpret_cast<const uint64_t*>(w_ih + (size_t)row0 * II);
        #pragma unroll
        for (int k = 0; k < 5; k++) wi0[k] = p[k];
    }
    if (is_rz) {
        const uint64_t* p = reinterpret_cast<const uint64_t*>(w_ih + (size_t)(HH + i) * II);
        #pragma unroll
        for (int k = 0; k < 5; k++) wi1[k] = p[k];
    }
    const float bh0 = b_hh[row0];
    const float bi0 = b_ih[row0];
    const float bh1 = is_rz ? b_hh[HH + i] : 0.0f;
    const float bi1 = is_rz ? b_ih[HH + i] : 0.0f;

    if (t < HH) hs[half][t] = 0.0f;
    float h_reg = 0.0f;                       // rz thread caches h[i]

    const float* xg = noise + (size_t)b * TT * II;
    float* outb = out + (size_t)b * TT * HH;

    #pragma unroll 1
    for (int o = t; o < CPOPS; o += TPB)
        cp16((uint32_t)__cvta_generic_to_shared(&xs[half][0][o * 4]), xg + o * 4);
    asm volatile("cp.async.commit_group;");

    int buf = 0;
    #pragma unroll 1
    for (int c = 0; c < NCH; ++c) {
        if (c + 1 < NCH) {
            #pragma unroll 1
            for (int o = t; o < CPOPS; o += TPB)
                cp16((uint32_t)__cvta_generic_to_shared(&xs[half][buf ^ 1][o * 4]),
                     xg + (size_t)(c + 1) * CHUNK * II + o * 4);
        }
        asm volatile("cp.async.commit_group;");
        asm volatile("cp.async.wait_group 1;");
        barh(half);   // chunk visible; also guards hs from previous chunk

        // x-dots for step 0
        float px0 = dot10(wi0, &xs[half][buf][0]) + bi0;
        float px1 = is_rz ? (dot10(wi1, &xs[half][buf][0]) + bi1) : 0.0f;

        #pragma unroll 1
        for (int s = 0; s < CHUNK; ++s) {
            // ---- load h once, packed ----
            ulonglong2 hv[16];
            {
                const ulonglong2* hp = reinterpret_cast<const ulonglong2*>(hs[half]);
                #pragma unroll
                for (int k = 0; k < 16; k++) hv[k] = hp[k];
            }

            float rr = 0.0f, zz = 0.0f;
            if (is_rz) {
                float ph_r = dot64(w0, hv) + bh0;
                float ph_z = dot64(w1, hv) + bh1;
                rr = sigm(ph_r + px0);           // local — before barrier
                zz = sigm(ph_z + px1);
            } else {
                float ph_n = dot64(w0, hv) + bh0;
                nh[half][i] = ph_n;
                nx[half][i] = px0;
            }
            barh(half);   // handoff: n-parts visible to rz threads

            if (is_rz) {
                float hn = nh[half][i];
                float xn = nx[half][i];
                float ng = tanh_fast(xn + rr * hn);
                float hnew = ng + zz * (h_reg - ng);
                h_reg = hnew;
                hs[half][i] = hnew;
                outb[(size_t)(c * CHUNK + s) * HH + i] = hnew;
            }

            // next step's x-dots (h-independent, fills activation shadow)
            if (s + 1 < CHUNK) {
                const float* x = &xs[half][buf][(s + 1) * II];
                px0 = dot10(wi0, x) + bi0;
                if (is_rz) px1 = dot10(wi1, x) + bi1;
            }
            barh(half);   // publish new h
        }
        buf ^= 1;
    }
}

extern "C" void kernel_launch(void* const* d_in, const int* in_sizes, int n_in,
                              void* d_out, int out_size) {
    const float* noise = (const float*)d_in[0];
    const float* w_ih  = (const float*)d_in[1];
    const float* w_hh  = (const float*)d_in[2];
    const float* b_ih  = (const float*)d_in[3];
    const float* b_hh  = (const float*)d_in[4];
    float* out = (float*)d_out;
    gru_kernel<<<BB / 2, NT>>>(noise, w_ih, w_hh, b_ih, b_hh, out);
}

// round 15
// speedup vs baseline: 1.3056x; 1.0037x over previous
#include <cuda_runtime.h>
#include <cstdint>

// GRU B=256, T=2048, I=10, H=64 (PyTorch gate order r,z,n).
// Two-kernel plan:
//   1) gi_kernel: gi[b][t][g] = noise[b,t,:].w_ih[g,:] + b_ih[g]  (400MB scratch)
//   2) gru_rec: recurrence with ONE thread per h-index owning all 3 w_hh rows
//      (r,z,n,h-update fully local); per step: 96 FFMA2 + 1 publish barrier.
//      128 CTAs x 128 thr = 2 batches x 64 threads -> 1 warp per SMSP.

#define BB 256
#define TT 2048
#define II 10
#define HH 64
#define GG 192
#define CHUNK 32
#define NCH (TT / CHUNK)                 // 64
#define CBYTES (CHUNK * GG * 4)          // 24576 B per chunk per batch
#define CPOPS (CBYTES / 16)              // 1536 cp16 per chunk per batch

__device__ float g_gi[(size_t)BB * TT * GG];   // 400MB scratch

__device__ __forceinline__ uint64_t fma2(uint64_t a, uint64_t b, uint64_t c) {
    uint64_t d;
    asm("fma.rn.f32x2 %0, %1, %2, %3;" : "=l"(d) : "l"(a), "l"(b), "l"(c));
    return d;
}
__device__ __forceinline__ void cp16(uint32_t saddr, const void* gptr) {
    asm volatile("cp.async.ca.shared.global [%0], [%1], 16;" :: "r"(saddr), "l"(gptr));
}
__device__ __forceinline__ float f2lo(uint64_t v) { return __uint_as_float((uint32_t)v); }
__device__ __forceinline__ float f2hi(uint64_t v) { return __uint_as_float((uint32_t)(v >> 32)); }
__device__ __forceinline__ void barh(int half) {
    asm volatile("bar.sync %0, %1;" :: "r"(half + 1), "r"(64) : "memory");
}
__device__ __forceinline__ float sigm(float x) { return 1.0f / (1.0f + __expf(-x)); }
__device__ __forceinline__ float tanh_fast(float x) {
    return 1.0f - 2.0f / (1.0f + __expf(2.0f * x));
}

// ---------------- kernel 1: input projection ----------------
__global__ __launch_bounds__(256) void gi_kernel(
    const float* __restrict__ noise,   // (B*T, I)
    const float* __restrict__ w_ih,    // (3H, I)
    const float* __restrict__ b_ih)    // (3H)
{
    size_t e = (size_t)blockIdx.x * 256 + threadIdx.x;   // over B*T*192
    if (e >= (size_t)BB * TT * GG) return;
    int g = (int)(e % GG);
    size_t bt = e / GG;
    const float* x = noise + bt * II;
    const float* w = w_ih + (size_t)g * II;
    float acc = b_ih[g];
    #pragma unroll
    for (int j = 0; j < II; j++) acc = fmaf(w[j], x[j], acc);
    g_gi[e] = acc;
}

// ---------------- kernel 2: recurrence ----------------
__global__ __launch_bounds__(128, 1) void gru_rec(
    const float* __restrict__ w_hh,    // (3H, H)
    const float* __restrict__ b_hh,    // (3H)
    float* __restrict__ out)           // (B, T, H)
{
    extern __shared__ __align__(16) float dyn[];
    // dyn layout: gis[2][2][CHUNK*GG]
    float* gis = dyn;
    __shared__ __align__(16) float hs[2][HH];

    const int half = threadIdx.x >> 6;       // batch within CTA
    const int i = threadIdx.x & (HH - 1);    // h index
    const int b = blockIdx.x * 2 + half;

    // --- all three w_hh rows for index i into registers (96 u64) ---
    uint64_t wr[32], wz[32], wn[32];
    {
        const uint64_t* p = reinterpret_cast<const uint64_t*>(w_hh + (size_t)i * HH);
        #pragma unroll
        for (int k = 0; k < 32; k++) wr[k] = p[k];
    }
    {
        const uint64_t* p = reinterpret_cast<const uint64_t*>(w_hh + (size_t)(HH + i) * HH);
        #pragma unroll
        for (int k = 0; k < 32; k++) wz[k] = p[k];
    }
    {
        const uint64_t* p = reinterpret_cast<const uint64_t*>(w_hh + (size_t)(2 * HH + i) * HH);
        #pragma unroll
        for (int k = 0; k < 32; k++) wn[k] = p[k];
    }
    const float bhr = b_hh[i];
    const float bhz = b_hh[HH + i];
    const float bhn = b_hh[2 * HH + i];

    hs[half][i] = 0.0f;
    float h_reg = 0.0f;

    const float* gib = g_gi + (size_t)b * TT * GG;
    float* outb = out + (size_t)b * TT * HH;
    float* mybuf0 = gis + (half * 2 + 0) * (CHUNK * GG);
    float* mybuf1 = gis + (half * 2 + 1) * (CHUNK * GG);

    // prefetch chunk 0
    #pragma unroll 1
    for (int o = i; o < CPOPS; o += HH)
        cp16((uint32_t)__cvta_generic_to_shared(mybuf0 + o * 4), gib + o * 4);
    asm volatile("cp.async.commit_group;");

    int buf = 0;
    #pragma unroll 1
    for (int c = 0; c < NCH; ++c) {
        float* cur = buf ? mybuf1 : mybuf0;
        float* nxt = buf ? mybuf0 : mybuf1;
        if (c + 1 < NCH) {
            const float* src = gib + (size_t)(c + 1) * CHUNK * GG;
            #pragma unroll 1
            for (int o = i; o < CPOPS; o += HH)
                cp16((uint32_t)__cvta_generic_to_shared(nxt + o * 4), src + o * 4);
        }
        asm volatile("cp.async.commit_group;");
        asm volatile("cp.async.wait_group 1;");
        barh(half);   // chunk visible to this batch's 64 threads

        #pragma unroll 1
        for (int s = 0; s < CHUNK; ++s) {
            // --- three 64-wide dots against shared h, fully local ---
            const ulonglong2* hp = reinterpret_cast<const ulonglong2*>(hs[half]);
            uint64_t ar0 = 0, ar1 = 0, az0 = 0, az1 = 0, an0 = 0, an1 = 0;
            #pragma unroll
            for (int k = 0; k < 16; k++) {
                ulonglong2 v = hp[k];
                ar0 = fma2(wr[2 * k],     v.x, ar0);
                ar1 = fma2(wr[2 * k + 1], v.y, ar1);
                az0 = fma2(wz[2 * k],     v.x, az0);
                az1 = fma2(wz[2 * k + 1], v.y, az1);
                an0 = fma2(wn[2 * k],     v.x, an0);
                an1 = fma2(wn[2 * k + 1], v.y, an1);
            }
            float dr = (f2lo(ar0) + f2hi(ar0)) + (f2lo(ar1) + f2hi(ar1));
            float dz = (f2lo(az0) + f2hi(az0)) + (f2lo(az1) + f2hi(az1));
            float dn = (f2lo(an0) + f2hi(an0)) + (f2lo(an1) + f2hi(an1));

            const float* gp = cur + s * GG;
            float gr = gp[i];
            float gz = gp[HH + i];
            float gn = gp[2 * HH + i];

            float r = sigm(gr + dr + bhr);
            float z = sigm(gz + dz + bhz);
            float n = tanh_fast(gn + r * (dn + bhn));
            float hnew = n + z * (h_reg - n);
            h_reg = hnew;
            hs[half][i] = hnew;
            outb[(size_t)(c * CHUNK + s) * HH + i] = hnew;
            barh(half);   // publish h before anyone's next-step load
        }
        buf ^= 1;
    }
}

extern "C" void kernel_launch(void* const* d_in, const int* in_sizes, int n_in,
                              void* d_out, int out_size) {
    const float* noise = (const float*)d_in[0];
    const float* w_ih  = (const float*)d_in[1];
    const float* w_hh  = (const float*)d_in[2];
    const float* b_ih  = (const float*)d_in[3];
    const float* b_hh  = (const float*)d_in[4];
    float* out = (float*)d_out;

    // kernel 1: input projection into g_gi
    size_t total = (size_t)BB * TT * GG;
    int blocks = (int)((total + 255) / 256);
    gi_kernel<<<blocks, 256>>>(noise, w_ih, b_ih);

    // kernel 2: recurrence (dynamic smem for gi chunks: 2 batches x 2 bufs)
    int dsm = 2 * 2 * CBYTES;   // 98304 B
    cudaFuncSetAttribute(gru_rec, cudaFuncAttributeMaxDynamicSharedMemorySize, dsm);
    gru_rec<<<BB / 2, 128, dsm>>>(w_hh, b_hh, out);
}

// round 17
// speedup vs baseline: 1.6360x; 1.2530x over previous
#include <cuda_runtime.h>
#include <cstdint>

// GRU B=256, T=2048, I=10, H=64 (PyTorch gate order r,z,n).
// grid=128, CTA=256 thr = 2 batches x 128 threads.
// Pair of adjacent lanes (side=t&1) owns h-index i=t>>1: each side holds
// 32-element halves of ALL THREE w_hh rows (r,z,n) in registers plus its
// half of the three w_ih rows. Dots are 48 FFMA2/thread; pair combines via
// shfl.xor 1. Double-buffered h => ONE 128-thread named barrier per step.
// x chunks via cp.async double buffering; x-dots pipelined one step ahead.

#define BB 256
#define TT 2048
#define II 10
#define HH 64
#define TPB 128                 // threads per batch
#define NT (2 * TPB)            // 256
#define CHUNK 64
#define NCH (TT / CHUNK)        // 32
#define CPOPS ((CHUNK * II * 4) / 16)   // 160 x 16B per chunk per batch

__device__ __forceinline__ uint64_t fma2(uint64_t a, uint64_t b, uint64_t c) {
    uint64_t d;
    asm("fma.rn.f32x2 %0, %1, %2, %3;" : "=l"(d) : "l"(a), "l"(b), "l"(c));
    return d;
}
__device__ __forceinline__ void cp16(uint32_t saddr, const void* gptr) {
    asm volatile("cp.async.ca.shared.global [%0], [%1], 16;" :: "r"(saddr), "l"(gptr));
}
__device__ __forceinline__ float f2lo(uint64_t v) { return __uint_as_float((uint32_t)v); }
__device__ __forceinline__ float f2hi(uint64_t v) { return __uint_as_float((uint32_t)(v >> 32)); }
__device__ __forceinline__ void barh(int half) {
    asm volatile("bar.sync %0, %1;" :: "r"(half + 1), "r"(TPB) : "memory");
}
__device__ __forceinline__ float sigm(float x) { return 1.0f / (1.0f + __expf(-x)); }
__device__ __forceinline__ float tanh_fast(float x) {
    return 1.0f - 2.0f / (1.0f + __expf(2.0f * x));
}

// 32-wide packed half-dot: wp = 16 f32x2 pairs, hv = 8 x ulonglong2
__device__ __forceinline__ float dot32(const uint64_t* __restrict__ wp,
                                       const ulonglong2* __restrict__ hv) {
    uint64_t a0 = 0ull, a1 = 0ull;
    #pragma unroll
    for (int k = 0; k < 8; k++) {
        ulonglong2 v = hv[k];
        a0 = fma2(wp[2 * k],     v.x, a0);
        a1 = fma2(wp[2 * k + 1], v.y, a1);
    }
    return (f2lo(a0) + f2hi(a0)) + (f2lo(a1) + f2hi(a1));
}

__global__ __launch_bounds__(NT, 1) void gru_kernel(
    const float* __restrict__ noise,   // (B, T, I)
    const float* __restrict__ w_ih,    // (3H, I)
    const float* __restrict__ w_hh,    // (3H, H)
    const float* __restrict__ b_ih,    // (3H)
    const float* __restrict__ b_hh,    // (3H)
    float* __restrict__ out)           // (B, T, H)
{
    const int half = threadIdx.x >> 7;        // batch within CTA
    const int t = threadIdx.x & (TPB - 1);    // 0..127
    const int side = t & 1;                   // 0: h[0:32), 1: h[32:64)
    const int i = t >> 1;                     // h index 0..63 (pair = adj lanes)
    const int b = blockIdx.x * 2 + half;

    __shared__ __align__(16) float hs[2][2][HH];   // [hbuf][half][i]
    __shared__ __align__(16) float xs[2][2][CHUNK * II];

    // ---- w_hh halves for all 3 gates: 16 u64 each ----
    uint64_t wr[16], wz[16], wn[16];
    {
        const uint64_t* p =
            reinterpret_cast<const uint64_t*>(w_hh + (size_t)i * HH + side * 32);
        #pragma unroll
        for (int k = 0; k < 16; k++) wr[k] = p[k];
    }
    {
        const uint64_t* p =
            reinterpret_cast<const uint64_t*>(w_hh + (size_t)(HH + i) * HH + side * 32);
        #pragma unroll
        for (int k = 0; k < 16; k++) wz[k] = p[k];
    }
    {
        const uint64_t* p =
            reinterpret_cast<const uint64_t*>(w_hh + (size_t)(2 * HH + i) * HH + side * 32);
        #pragma unroll
        for (int k = 0; k < 16; k++) wn[k] = p[k];
    }
    // ---- w_ih halves (5 scalars per gate) ----
    float wir[5], wiz[5], win[5];
    #pragma unroll
    for (int j = 0; j < 5; j++) {
        wir[j] = w_ih[(size_t)i * II + side * 5 + j];
        wiz[j] = w_ih[(size_t)(HH + i) * II + side * 5 + j];
        win[j] = w_ih[(size_t)(2 * HH + i) * II + side * 5 + j];
    }
    // biases folded into side 0's partials
    const float br = (side == 0) ? (b_hh[i] + b_ih[i]) : 0.0f;
    const float bz = (side == 0) ? (b_hh[HH + i] + b_ih[HH + i]) : 0.0f;
    const float bhn = (side == 0) ? b_hh[2 * HH + i] : 0.0f;
    const float bin = (side == 0) ? b_ih[2 * HH + i] : 0.0f;

    if (t < HH) { hs[0][half][t] = 0.0f; hs[1][half][t] = 0.0f; }
    float h_reg = 0.0f;                       // side0 caches h[i]

    const float* xg = noise + (size_t)b * TT * II;
    float* outb = out + (size_t)b * TT * HH;

    #pragma unroll 1
    for (int o = t; o < CPOPS; o += TPB)
        cp16((uint32_t)__cvta_generic_to_shared(&xs[half][0][o * 4]), xg + o * 4);
    asm volatile("cp.async.commit_group;");

    int buf = 0;
    int hb = 0;
    #pragma unroll 1
    for (int c = 0; c < NCH; ++c) {
        if (c + 1 < NCH) {
            const float* src = xg + (size_t)(c + 1) * CHUNK * II;
            #pragma unroll 1
            for (int o = t; o < CPOPS; o += TPB)
                cp16((uint32_t)__cvta_generic_to_shared(&xs[half][buf ^ 1][o * 4]),
                     src + o * 4);
        }
        asm volatile("cp.async.commit_group;");
        asm volatile("cp.async.wait_group 1;");
        barh(half);   // chunk visible

        // x-dots for step 0 of this chunk
        float pxr, pxz, pxn;
        {
            const float* x = &xs[half][buf][side * 5];
            float ar = 0, az = 0, an = 0;
            #pragma unroll
            for (int j = 0; j < 5; j++) {
                ar = fmaf(wir[j], x[j], ar);
                az = fmaf(wiz[j], x[j], az);
                an = fmaf(win[j], x[j], an);
            }
            pxr = ar; pxz = az; pxn = an;
        }

        #pragma unroll 1
        for (int s = 0; s < CHUNK; ++s) {
            // ---- three 32-wide half-dots against h[hb] ----
            const ulonglong2* hv =
                reinterpret_cast<const ulonglong2*>(&hs[hb][half][side * 32]);
            ulonglong2 hreg[8];
            #pragma unroll
            for (int k = 0; k < 8; k++) hreg[k] = hv[k];

            float vr = dot32(wr, hreg) + pxr + br;       // r pre-act partial
            float vz = dot32(wz, hreg) + pxz + bz;       // z pre-act partial
            float vnh = dot32(wn, hreg) + bhn;           // n h-part partial
            float vnx = pxn + bin;                       // n x-part partial

            // pair combine (adjacent lanes)
            vr  += __shfl_xor_sync(0xffffffffu, vr, 1);
            vz  += __shfl_xor_sync(0xffffffffu, vz, 1);
            vnh += __shfl_xor_sync(0xffffffffu, vnh, 1);
            vnx += __shfl_xor_sync(0xffffffffu, vnx, 1);

            if (side == 0) {
                float r = sigm(vr);
                float z = sigm(vz);
                float n = tanh_fast(vnx + r * vnh);
                float hnew = n + z * (h_reg - n);
                h_reg = hnew;
                hs[hb ^ 1][half][i] = hnew;
                outb[(size_t)(c * CHUNK + s) * HH + i] = hnew;
            }

            // pipelined x-dots for next step (activation shadow)
            if (s + 1 < CHUNK) {
                const float* x = &xs[half][buf][(s + 1) * II + side * 5];
                float ar = 0, az = 0, an = 0;
                #pragma unroll
                for (int j = 0; j < 5; j++) {
                    ar = fmaf(wir[j], x[j], ar);
                    az = fmaf(wiz[j], x[j], az);
                    an = fmaf(win[j], x[j], an);
                }
                pxr = ar; pxz = az; pxn = an;
            }

            barh(half);   // publish h[hb^1]; single barrier per step
            hb ^= 1;
        }
        buf ^= 1;
    }
}

extern "C" void kernel_launch(void* const* d_in, const int* in_sizes, int n_in,
                              void* d_out, int out_size) {
    const float* noise = (const float*)d_in[0];
    const float* w_ih  = (const float*)d_in[1];
    const float* w_hh  = (const float*)d_in[2];
    const float* b_ih  = (const float*)d_in[3];
    const float* b_hh  = (const float*)d_in[4];
    float* out = (float*)d_out;
    gru_kernel<<<BB / 2, NT>>>(noise, w_ih, w_hh, b_ih, b_hh, out);
}